// round 11
// baseline (speedup 1.0000x reference)
#include <cuda_runtime.h>
#include <cuda_bf16.h>
#include <cstdint>

#define N_TOK   49
#define NHEADS  4
#define NWIN    64
#define THREADS 768

// ---- smem byte offsets ----
#define OFF_XH   0          // 16384
#define OFF_XL   16384      // 16384
#define OFF_QFH  32768      // 16384  q A-frags hi  [h][mt4][kc2][lane][reg4] u32
#define OFF_QFL  49152      // 16384
#define OFF_KFH  65536      // 14336  k B-frags hi  [h][nt7][kc2][lane][reg2] u32
#define OFF_KFL  79872      // 14336
#define OFF_VFH  94208      // 16384  v B-frags hi  [h][kck4][ntd4][lane][reg2] u32
#define OFF_VFL  110592     // 16384
#define OFF_BM   126976     // 4*2401 f32 fused bias+mask  -> 165392
#define OFF_BVEC 165392     // 384 f32
#define SMEM_TOTAL 166928

// W in fragment layout: [c8(48)][kc(8)][lane(32)][reg(2)] u32 (bf16 pairs)
__device__ __align__(16) uint32_t g_wfh[48 * 8 * 32 * 2];
__device__ __align__(16) uint32_t g_wfl[48 * 8 * 32 * 2];

__device__ __forceinline__ void mma16816(float* c, const uint32_t* a, const uint32_t* b) {
    asm volatile(
        "mma.sync.aligned.m16n8k16.row.col.f32.bf16.bf16.f32 "
        "{%0,%1,%2,%3}, {%4,%5,%6,%7}, {%8,%9}, {%0,%1,%2,%3};"
        : "+f"(c[0]), "+f"(c[1]), "+f"(c[2]), "+f"(c[3])
        : "r"(a[0]), "r"(a[1]), "r"(a[2]), "r"(a[3]), "r"(b[0]), "r"(b[1]));
}

__device__ __forceinline__ void split_bf16(float v, __nv_bfloat16& h, __nv_bfloat16& l) {
    h = __float2bfloat16(v);
    l = __float2bfloat16(v - __bfloat162float(h));
}

__device__ __forceinline__ void pack_hl(float a, float b, uint32_t& ph, uint32_t& pl) {
    __nv_bfloat16 ha, la, hb, lb;
    split_bf16(a, ha, la);
    split_bf16(b, hb, lb);
    ph = (uint32_t)__bfloat16_as_ushort(ha) | ((uint32_t)__bfloat16_as_ushort(hb) << 16);
    pl = (uint32_t)__bfloat16_as_ushort(la) | ((uint32_t)__bfloat16_as_ushort(lb) << 16);
}

// ---- prep: W (384x128 f32) -> bf16 hi/lo fragment-layout tiles ----
__global__ void prep_w(const float* __restrict__ W) {
    for (int i = blockIdx.x * blockDim.x + threadIdx.x; i < 384 * 64;
         i += gridDim.x * blockDim.x) {
        const int o = i >> 6, kp = i & 63, k = kp * 2;
        const float w0 = W[o * 128 + k], w1 = W[o * 128 + k + 1];
        __nv_bfloat16 h0, l0, h1, l1;
        split_bf16(w0, h0, l0);
        split_bf16(w1, h1, l1);
        const uint32_t ph = (uint32_t)__bfloat16_as_ushort(h0)
                          | ((uint32_t)__bfloat16_as_ushort(h1) << 16);
        const uint32_t pl = (uint32_t)__bfloat16_as_ushort(l0)
                          | ((uint32_t)__bfloat16_as_ushort(l1) << 16);
        const int c8 = o >> 3, g = o & 7, kc = k >> 4, kk = k & 15;
        const int reg = (kk >= 8), j = (kk & 7) >> 1;
        const int pos = (((c8 * 8 + kc) * 32) + g * 4 + j) * 2 + reg;
        g_wfh[pos] = ph;
        g_wfl[pos] = pl;
    }
}

__global__ __launch_bounds__(THREADS, 1)
void win_attn_kernel(const float* __restrict__ x, const float* __restrict__ mask,
                     const float* __restrict__ bvec, const float* __restrict__ rel_table,
                     float* __restrict__ out)
{
    extern __shared__ char sm[];
    float* bvec_s = (float*)(sm + OFF_BVEC);
    float* bm_s   = (float*)(sm + OFF_BM);

    const int t = threadIdx.x, wid = t >> 5, lane = t & 31;
    const int g = lane >> 2, tq = lane & 3;
    const int b = blockIdx.x;

    // ---- phase 0: zero v-frags, stage bvec, fused bias+mask, x frags ----
    {
        uint4 z = make_uint4(0, 0, 0, 0);
        uint4* v4 = (uint4*)(sm + OFF_VFH);
        for (int i = t; i < 2048; i += THREADS) v4[i] = z;  // VFH + VFL (32KB)
    }
    for (int i = t; i < 384; i += THREADS) bvec_s[i] = bvec[i];
    {
        // bm[h][r][m] = rel_table[ridx(r,m)*4 + h] + mask[win][r][m]
        const float* mw = mask + (size_t)(b & (NWIN - 1)) * 2401;
        for (int i = t; i < NHEADS * 2401; i += THREADS) {
            const int h = i / 2401, j = i - h * 2401;
            const int r = j / 49, m = j - r * 49;
            const int ridx = (r / 7 - m / 7 + 6) * 13 + (r % 7 - m % 7 + 6);
            bm_s[i] = __ldg(&rel_table[ridx * NHEADS + h]) + __ldg(&mw[j]);
        }
    }
    {
        const float4* xg = (const float4*)(x + (size_t)b * 6272);
        uint32_t* xh = (uint32_t*)(sm + OFF_XH);
        uint32_t* xl = (uint32_t*)(sm + OFF_XL);
        for (int i = t; i < 64 * 32; i += THREADS) {
            const int r = i >> 5, k0 = (i & 31) * 4;
            float4 v = make_float4(0.f, 0.f, 0.f, 0.f);
            if (r < N_TOK) v = xg[r * 32 + (i & 31)];
            __nv_bfloat16 h0, l0, h1, l1, h2, l2, h3, l3;
            split_bf16(v.x, h0, l0); split_bf16(v.y, h1, l1);
            split_bf16(v.z, h2, l2); split_bf16(v.w, h3, l3);
            const uint32_t ph01 = (uint32_t)__bfloat16_as_ushort(h0) | ((uint32_t)__bfloat16_as_ushort(h1) << 16);
            const uint32_t ph23 = (uint32_t)__bfloat16_as_ushort(h2) | ((uint32_t)__bfloat16_as_ushort(h3) << 16);
            const uint32_t pl01 = (uint32_t)__bfloat16_as_ushort(l0) | ((uint32_t)__bfloat16_as_ushort(l1) << 16);
            const uint32_t pl23 = (uint32_t)__bfloat16_as_ushort(l2) | ((uint32_t)__bfloat16_as_ushort(l3) << 16);
            const int mt = r >> 4, r16 = r & 15, g8 = r16 & 7;
            const int kc = k0 >> 4, kk = k0 & 15;
            const int reg = (r16 >= 8 ? 1 : 0) + (kk >= 8 ? 2 : 0);
            const int jj = (kk & 7) >> 1;
            const int base = (((mt * 8 + kc) * 32) + g8 * 4 + jj) * 4 + reg;
            xh[base] = ph01; xh[base + 4] = ph23;
            xl[base] = pl01; xl[base + 4] = pl23;
        }
    }
    __syncthreads();

    // ---- phase 1: projection, one 64x16 warp tile per warp (24 warps) ----
    {
        float c[4][2][4];
        #pragma unroll
        for (int mt = 0; mt < 4; mt++)
            #pragma unroll
            for (int j = 0; j < 2; j++)
                #pragma unroll
                for (int e = 0; e < 4; e++) c[mt][j][e] = 0.f;

        const uint2* wfh = (const uint2*)g_wfh;
        const uint2* wfl = (const uint2*)g_wfl;
        #pragma unroll
        for (int kc = 0; kc < 8; kc++) {
            uint4 ah[4], al[4];
            #pragma unroll
            for (int mt = 0; mt < 4; mt++) {
                const int idx = (((mt * 8 + kc) * 32) + lane) << 4;
                ah[mt] = *(const uint4*)(sm + OFF_XH + idx);
                al[mt] = *(const uint4*)(sm + OFF_XL + idx);
            }
            uint2 bh[2], bl[2];
            #pragma unroll
            for (int j = 0; j < 2; j++) {
                const int idx = ((wid * 2 + j) * 8 + kc) * 32 + lane;
                bh[j] = __ldg(&wfh[idx]);
                bl[j] = __ldg(&wfl[idx]);
            }
            #pragma unroll
            for (int mt = 0; mt < 4; mt++)
                #pragma unroll
                for (int j = 0; j < 2; j++) {
                    mma16816(c[mt][j], (const uint32_t*)&ah[mt], (const uint32_t*)&bh[j]);
                    mma16816(c[mt][j], (const uint32_t*)&ah[mt], (const uint32_t*)&bl[j]);
                    mma16816(c[mt][j], (const uint32_t*)&al[mt], (const uint32_t*)&bh[j]);
                }
        }

        // epilogue: +bias, split hi/lo, store into q/k/v FRAGMENT layouts
        const float scale = 0.17677669529663687f;  // 1/sqrt(32), folded into q
        #pragma unroll
        for (int j = 0; j < 2; j++)
            #pragma unroll
            for (int e = 0; e < 4; e++) {
                const int o = wid * 16 + j * 8 + tq * 2 + (e & 1);
                const int h = o / 96, rem = o - 96 * h;
                const int d = rem / 3, which = rem - 3 * d;
                const float bo = bvec_s[o];
                #pragma unroll
                for (int mt = 0; mt < 4; mt++) {
                    const int n = mt * 16 + g + (e >= 2 ? 8 : 0);
                    if (n >= N_TOK) continue;
                    float val = c[mt][j][e] + bo;
                    if (which == 0) val *= scale;
                    __nv_bfloat16 hi, lo;
                    split_bf16(val, hi, lo);
                    int addr;
                    if (which == 0) {        // q A-frag
                        const int li = ((n & 7) << 2) | ((d & 7) >> 1);
                        const int reg = ((n & 15) >= 8 ? 1 : 0) + ((d & 15) >= 8 ? 2 : 0);
                        addr = ((((h * 4 + (n >> 4)) * 2 + (d >> 4)) * 32 + li) * 4 + reg) * 4 + (d & 1) * 2;
                        *(__nv_bfloat16*)(sm + OFF_QFH + addr) = hi;
                        *(__nv_bfloat16*)(sm + OFF_QFL + addr) = lo;
                    } else if (which == 1) { // k B-frag (K-dim = d)
                        const int li = ((n & 7) << 2) | ((d & 7) >> 1);
                        const int reg = ((d & 15) >= 8 ? 1 : 0);
                        addr = ((((h * 7 + (n >> 3)) * 2 + (d >> 4)) * 32 + li) * 2 + reg) * 4 + (d & 1) * 2;
                        *(__nv_bfloat16*)(sm + OFF_KFH + addr) = hi;
                        *(__nv_bfloat16*)(sm + OFF_KFL + addr) = lo;
                    } else {                 // v B-frag (K-dim = key n, N-dim = d)
                        const int li = ((d & 7) << 2) | ((n & 7) >> 1);
                        const int reg = ((n & 15) >= 8 ? 1 : 0);
                        addr = ((((h * 4 + (n >> 4)) * 4 + (d >> 3)) * 32 + li) * 2 + reg) * 4 + (n & 1) * 2;
                        *(__nv_bfloat16*)(sm + OFF_VFH + addr) = hi;
                        *(__nv_bfloat16*)(sm + OFF_VFL + addr) = lo;
                    }
                }
            }
    }
    __syncthreads();

    // ---- phase 2: attention, one (head, 16-row tile) per warp (warps 0-15) ----
    if (wid < 16) {
        const int h = wid >> 2, mt = wid & 3;
        const int r0 = mt * 16 + g, r1 = r0 + 8;
        const float* bmh = bm_s + h * 2401;

        // q A-frags
        uint4 ah[2], al[2];
        #pragma unroll
        for (int kc = 0; kc < 2; kc++) {
            const int idx = (((h * 4 + mt) * 2 + kc) * 32 + lane) << 4;
            ah[kc] = *(const uint4*)(sm + OFF_QFH + idx);
            al[kc] = *(const uint4*)(sm + OFF_QFL + idx);
        }

        // S = q k^T  (7 n-tiles of 8 keys)
        float c[7][4];
        #pragma unroll
        for (int nt = 0; nt < 7; nt++)
            #pragma unroll
            for (int e = 0; e < 4; e++) c[nt][e] = 0.f;

        #pragma unroll
        for (int nt = 0; nt < 7; nt++)
            #pragma unroll
            for (int kc = 0; kc < 2; kc++) {
                const int idx = (((h * 7 + nt) * 2 + kc) * 32 + lane) << 3;
                const uint2 bh = *(const uint2*)(sm + OFF_KFH + idx);
                const uint2 bl = *(const uint2*)(sm + OFF_KFL + idx);
                mma16816(c[nt], (const uint32_t*)&ah[kc], (const uint32_t*)&bh);
                mma16816(c[nt], (const uint32_t*)&ah[kc], (const uint32_t*)&bl);
                mma16816(c[nt], (const uint32_t*)&al[kc], (const uint32_t*)&bh);
            }

        // fused bias+mask in c-frag layout
        #pragma unroll
        for (int nt = 0; nt < 7; nt++)
            #pragma unroll
            for (int e = 0; e < 4; e++) {
                const int r = (e >= 2) ? r1 : r0;
                const int m = nt * 8 + tq * 2 + (e & 1);
                if (m < N_TOK && r < N_TOK)
                    c[nt][e] += bmh[r * 49 + m];
                else
                    c[nt][e] = -1e30f;
            }

        // softmax: rows r0 (e=0,1) and r1 (e=2,3); reduce across 4-lane group
        float mx0 = -1e30f, mx1 = -1e30f;
        #pragma unroll
        for (int nt = 0; nt < 7; nt++) {
            mx0 = fmaxf(mx0, fmaxf(c[nt][0], c[nt][1]));
            mx1 = fmaxf(mx1, fmaxf(c[nt][2], c[nt][3]));
        }
        mx0 = fmaxf(mx0, __shfl_xor_sync(~0u, mx0, 1));
        mx0 = fmaxf(mx0, __shfl_xor_sync(~0u, mx0, 2));
        mx1 = fmaxf(mx1, __shfl_xor_sync(~0u, mx1, 1));
        mx1 = fmaxf(mx1, __shfl_xor_sync(~0u, mx1, 2));
        float s0 = 0.f, s1 = 0.f;
        #pragma unroll
        for (int nt = 0; nt < 7; nt++) {
            c[nt][0] = __expf(c[nt][0] - mx0); s0 += c[nt][0];
            c[nt][1] = __expf(c[nt][1] - mx0); s0 += c[nt][1];
            c[nt][2] = __expf(c[nt][2] - mx1); s1 += c[nt][2];
            c[nt][3] = __expf(c[nt][3] - mx1); s1 += c[nt][3];
        }
        s0 += __shfl_xor_sync(~0u, s0, 1);
        s0 += __shfl_xor_sync(~0u, s0, 2);
        s1 += __shfl_xor_sync(~0u, s1, 1);
        s1 += __shfl_xor_sync(~0u, s1, 2);
        const float inv0 = 1.f / s0, inv1 = 1.f / s1;
        #pragma unroll
        for (int nt = 0; nt < 7; nt++) {
            c[nt][0] *= inv0; c[nt][1] *= inv0;
            c[nt][2] *= inv1; c[nt][3] *= inv1;
        }

        // PV: P (c-frags -> A-frags in registers) x V (B-frags)
        float o_[4][4];
        #pragma unroll
        for (int nd = 0; nd < 4; nd++)
            #pragma unroll
            for (int e = 0; e < 4; e++) o_[nd][e] = 0.f;

        #pragma unroll
        for (int kck = 0; kck < 4; kck++) {
            uint32_t pah[4], pal[4];
            pack_hl(c[2 * kck][0],     c[2 * kck][1],     pah[0], pal[0]);
            pack_hl(c[2 * kck][2],     c[2 * kck][3],     pah[1], pal[1]);
            pack_hl(c[2 * kck + 1][0], c[2 * kck + 1][1], pah[2], pal[2]);
            pack_hl(c[2 * kck + 1][2], c[2 * kck + 1][3], pah[3], pal[3]);
            #pragma unroll
            for (int nd = 0; nd < 4; nd++) {
                const int idx = (((h * 4 + kck) * 4 + nd) * 32 + lane) << 3;
                const uint2 vh = *(const uint2*)(sm + OFF_VFH + idx);
                const uint2 vl = *(const uint2*)(sm + OFF_VFL + idx);
                mma16816(o_[nd], pah, (const uint32_t*)&vh);
                mma16816(o_[nd], pah, (const uint32_t*)&vl);
                mma16816(o_[nd], pal, (const uint32_t*)&vh);
            }
        }

        // writeback
        float* ob = out + (size_t)b * 6272 + h * 32;
        #pragma unroll
        for (int nd = 0; nd < 4; nd++) {
            const int d0 = nd * 8 + tq * 2;
            if (r0 < N_TOK)
                *(float2*)(ob + r0 * 128 + d0) = make_float2(o_[nd][0], o_[nd][1]);
            if (r1 < N_TOK)
                *(float2*)(ob + r1 * 128 + d0) = make_float2(o_[nd][2], o_[nd][3]);
        }
    }
}

extern "C" void kernel_launch(void* const* d_in, const int* in_sizes, int n_in,
                              void* d_out, int out_size)
{
    const float* x    = (const float*)d_in[0];
    const float* mask = (const float*)d_in[1];
    const float* W    = (const float*)d_in[2];
    const float* bvec = (const float*)d_in[3];
    const float* rel  = (const float*)d_in[4];
    float* out = (float*)d_out;

    prep_w<<<96, 256>>>(W);
    cudaFuncSetAttribute(win_attn_kernel,
                         cudaFuncAttributeMaxDynamicSharedMemorySize, SMEM_TOTAL);
    win_attn_kernel<<<4096, THREADS, SMEM_TOTAL>>>(x, mask, bvec, rel, out);
}

// round 12
// speedup vs baseline: 1.2250x; 1.2250x over previous
#include <cuda_runtime.h>
#include <cuda_bf16.h>
#include <cstdint>

#define N_TOK   49
#define NHEADS  4
#define NWIN    64
#define THREADS 512

// ---- smem byte offsets ----
#define OFF_XH   0          // 16384
#define OFF_XL   16384      // 16384
#define OFF_QFH  32768      // 16384  q A-frags hi  [h][mt4][kc2][lane][reg4] u32
#define OFF_QFL  49152      // 16384
#define OFF_KFH  65536      // 14336  k B-frags hi  [h][nt7][kc2][lane][reg2] u32
#define OFF_KFL  79872      // 14336
#define OFF_VFH  94208      // 16384  v B-frags hi  [h][kck4][ntd4][lane][reg2] u32
#define OFF_VFL  110592     // 16384
#define OFF_MASK 126976     // 2401 f32
#define OFF_RIDX 136580     // 2401 u8
#define OFF_REL  139000     // 676 f32
#define OFF_BVEC 141704     // 384 f32 (PERMUTED order o' = which*128 + h*32 + d)
#define SMEM_TOTAL 143240

// W in fragment layout with PERMUTED columns: o' = which*128 + h*32 + d
// [c8(48)][kc(8)][lane(32)][reg(2)] u32 (bf16 pairs)
__device__ __align__(16) uint32_t g_wfh[48 * 8 * 32 * 2];
__device__ __align__(16) uint32_t g_wfl[48 * 8 * 32 * 2];

__device__ __forceinline__ void mma16816(float* c, const uint32_t* a, const uint32_t* b) {
    asm volatile(
        "mma.sync.aligned.m16n8k16.row.col.f32.bf16.bf16.f32 "
        "{%0,%1,%2,%3}, {%4,%5,%6,%7}, {%8,%9}, {%0,%1,%2,%3};"
        : "+f"(c[0]), "+f"(c[1]), "+f"(c[2]), "+f"(c[3])
        : "r"(a[0]), "r"(a[1]), "r"(a[2]), "r"(a[3]), "r"(b[0]), "r"(b[1]));
}

__device__ __forceinline__ void split_bf16(float v, __nv_bfloat16& h, __nv_bfloat16& l) {
    h = __float2bfloat16(v);
    l = __float2bfloat16(v - __bfloat162float(h));
}

__device__ __forceinline__ void pack_hl(float a, float b, uint32_t& ph, uint32_t& pl) {
    __nv_bfloat16 ha, la, hb, lb;
    split_bf16(a, ha, la);
    split_bf16(b, hb, lb);
    ph = (uint32_t)__bfloat16_as_ushort(ha) | ((uint32_t)__bfloat16_as_ushort(hb) << 16);
    pl = (uint32_t)__bfloat16_as_ushort(la) | ((uint32_t)__bfloat16_as_ushort(lb) << 16);
}

__device__ __forceinline__ int permute_col(int o) {
    // torch split order o = h*96 + d*3 + which  ->  o' = which*128 + h*32 + d
    const int h = o / 96, rem = o - 96 * h;
    const int d = rem / 3, which = rem - 3 * d;
    return which * 128 + h * 32 + d;
}

// ---- prep: W (384x128 f32) -> bf16 hi/lo fragment tiles, column-permuted ----
__global__ void prep_w(const float* __restrict__ W) {
    for (int i = blockIdx.x * blockDim.x + threadIdx.x; i < 384 * 64;
         i += gridDim.x * blockDim.x) {
        const int o = i >> 6, kp = i & 63, k = kp * 2;
        const float w0 = W[o * 128 + k], w1 = W[o * 128 + k + 1];
        __nv_bfloat16 h0, l0, h1, l1;
        split_bf16(w0, h0, l0);
        split_bf16(w1, h1, l1);
        const uint32_t ph = (uint32_t)__bfloat16_as_ushort(h0)
                          | ((uint32_t)__bfloat16_as_ushort(h1) << 16);
        const uint32_t pl = (uint32_t)__bfloat16_as_ushort(l0)
                          | ((uint32_t)__bfloat16_as_ushort(l1) << 16);
        const int op = permute_col(o);
        const int c8 = op >> 3, g = op & 7, kc = k >> 4, kk = k & 15;
        const int reg = (kk >= 8), j = (kk & 7) >> 1;
        const int pos = (((c8 * 8 + kc) * 32) + g * 4 + j) * 2 + reg;
        g_wfh[pos] = ph;
        g_wfl[pos] = pl;
    }
}

__global__ __launch_bounds__(THREADS, 1)
void win_attn_kernel(const float* __restrict__ x, const float* __restrict__ mask,
                     const float* __restrict__ bvec, const float* __restrict__ rel_table,
                     float* __restrict__ out)
{
    extern __shared__ char sm[];
    float* bvec_s = (float*)(sm + OFF_BVEC);
    float* rel_s  = (float*)(sm + OFF_REL);
    float* mask_s = (float*)(sm + OFF_MASK);
    unsigned char* ridx_s = (unsigned char*)(sm + OFF_RIDX);

    const int t = threadIdx.x, wid = t >> 5, lane = t & 31;
    const int g = lane >> 2, tq = lane & 3;
    const int b = blockIdx.x;

    // ---- phase 0: zero v-frags, stage tables (bvec permuted) + x frags ----
    {
        uint4 z = make_uint4(0, 0, 0, 0);
        uint4* v4 = (uint4*)(sm + OFF_VFH);
        for (int i = t; i < 2048; i += THREADS) v4[i] = z;  // VFH + VFL (32KB)
    }
    for (int i = t; i < 384; i += THREADS) bvec_s[permute_col(i)] = bvec[i];
    for (int i = t; i < 676; i += THREADS) rel_s[i] = rel_table[i];
    {
        const float* mw = mask + (size_t)(b & (NWIN - 1)) * 2401;
        for (int i = t; i < 2401; i += THREADS) {
            mask_s[i] = mw[i];
            const int n = i / 49, m = i - n * 49;
            ridx_s[i] = (unsigned char)((n / 7 - m / 7 + 6) * 13 + (n % 7 - m % 7 + 6));
        }
    }
    {
        const float4* xg = (const float4*)(x + (size_t)b * 6272);
        uint32_t* xh = (uint32_t*)(sm + OFF_XH);
        uint32_t* xl = (uint32_t*)(sm + OFF_XL);
        for (int i = t; i < 64 * 32; i += THREADS) {
            const int r = i >> 5, k0 = (i & 31) * 4;
            float4 v = make_float4(0.f, 0.f, 0.f, 0.f);
            if (r < N_TOK) v = xg[r * 32 + (i & 31)];
            __nv_bfloat16 h0, l0, h1, l1, h2, l2, h3, l3;
            split_bf16(v.x, h0, l0); split_bf16(v.y, h1, l1);
            split_bf16(v.z, h2, l2); split_bf16(v.w, h3, l3);
            const uint32_t ph01 = (uint32_t)__bfloat16_as_ushort(h0) | ((uint32_t)__bfloat16_as_ushort(h1) << 16);
            const uint32_t ph23 = (uint32_t)__bfloat16_as_ushort(h2) | ((uint32_t)__bfloat16_as_ushort(h3) << 16);
            const uint32_t pl01 = (uint32_t)__bfloat16_as_ushort(l0) | ((uint32_t)__bfloat16_as_ushort(l1) << 16);
            const uint32_t pl23 = (uint32_t)__bfloat16_as_ushort(l2) | ((uint32_t)__bfloat16_as_ushort(l3) << 16);
            const int mt = r >> 4, r16 = r & 15, g8 = r16 & 7;
            const int kc = k0 >> 4, kk = k0 & 15;
            const int reg = (r16 >= 8 ? 1 : 0) + (kk >= 8 ? 2 : 0);
            const int jj = (kk & 7) >> 1;
            const int base = (((mt * 8 + kc) * 32) + g8 * 4 + jj) * 4 + reg;
            xh[base] = ph01; xh[base + 4] = ph23;
            xl[base] = pl01; xl[base + 4] = pl23;
        }
    }
    __syncthreads();

    // ---- phase 1: projection, one 64x24 warp tile per warp ----
    {
        float c[4][3][4];
        #pragma unroll
        for (int mt = 0; mt < 4; mt++)
            #pragma unroll
            for (int j = 0; j < 3; j++)
                #pragma unroll
                for (int e = 0; e < 4; e++) c[mt][j][e] = 0.f;

        const uint2* wfh = (const uint2*)g_wfh;
        const uint2* wfl = (const uint2*)g_wfl;
        #pragma unroll
        for (int kc = 0; kc < 8; kc++) {
            uint4 ah[4], al[4];
            #pragma unroll
            for (int mt = 0; mt < 4; mt++) {
                const int idx = (((mt * 8 + kc) * 32) + lane) << 4;
                ah[mt] = *(const uint4*)(sm + OFF_XH + idx);
                al[mt] = *(const uint4*)(sm + OFF_XL + idx);
            }
            uint2 bh[3], bl[3];
            #pragma unroll
            for (int j = 0; j < 3; j++) {
                const int idx = ((wid * 3 + j) * 8 + kc) * 32 + lane;
                bh[j] = __ldg(&wfh[idx]);
                bl[j] = __ldg(&wfl[idx]);
            }
            #pragma unroll
            for (int mt = 0; mt < 4; mt++)
                #pragma unroll
                for (int j = 0; j < 3; j++) {
                    mma16816(c[mt][j], (const uint32_t*)&ah[mt], (const uint32_t*)&bh[j]);
                    mma16816(c[mt][j], (const uint32_t*)&ah[mt], (const uint32_t*)&bl[j]);
                    mma16816(c[mt][j], (const uint32_t*)&al[mt], (const uint32_t*)&bh[j]);
                }
        }

        // epilogue (permuted columns): per j-tile a single which/h; (e,e+1) = (d,d+1) u32 granule
        const float scale = 0.17677669529663687f;  // 1/sqrt(32), folded into q
        #pragma unroll
        for (int j = 0; j < 3; j++) {
            const int ocol  = wid * 24 + j * 8 + tq * 2;  // even permuted col
            const int which = ocol >> 7;
            const int h     = (ocol >> 5) & 3;
            const int d0    = ocol & 31;
            const float b0 = bvec_s[ocol], b1 = bvec_s[ocol + 1];
            #pragma unroll
            for (int mt = 0; mt < 4; mt++) {
                #pragma unroll
                for (int half = 0; half < 2; half++) {
                    const int n = mt * 16 + g + half * 8;
                    if (n >= N_TOK) continue;
                    float v0 = c[mt][j][half * 2 + 0] + b0;
                    float v1 = c[mt][j][half * 2 + 1] + b1;
                    if (which == 0) { v0 *= scale; v1 *= scale; }
                    if (which == 0) {        // q A-frag: one u32 (hi) + one u32 (lo)
                        uint32_t ph, pl;
                        pack_hl(v0, v1, ph, pl);
                        const int li = ((n & 7) << 2) | ((d0 & 7) >> 1);
                        const int reg = ((n & 15) >= 8 ? 1 : 0) + ((d0 & 15) >= 8 ? 2 : 0);
                        const int addr = ((((h * 4 + (n >> 4)) * 2 + (d0 >> 4)) * 32 + li) * 4 + reg) * 4;
                        *(uint32_t*)(sm + OFF_QFH + addr) = ph;
                        *(uint32_t*)(sm + OFF_QFL + addr) = pl;
                    } else if (which == 1) { // k B-frag: one u32 + one u32
                        uint32_t ph, pl;
                        pack_hl(v0, v1, ph, pl);
                        const int li = ((n & 7) << 2) | ((d0 & 7) >> 1);
                        const int reg = ((d0 & 15) >= 8 ? 1 : 0);
                        const int addr = ((((h * 7 + (n >> 3)) * 2 + (d0 >> 4)) * 32 + li) * 2 + reg) * 4;
                        *(uint32_t*)(sm + OFF_KFH + addr) = ph;
                        *(uint32_t*)(sm + OFF_KFL + addr) = pl;
                    } else {                 // v B-frag: granule pairs over n -> 2x bf16 stores
                        __nv_bfloat16 hi0, lo0, hi1, lo1;
                        split_bf16(v0, hi0, lo0);
                        split_bf16(v1, hi1, lo1);
                        const int reg = ((n & 15) >= 8 ? 1 : 0);
                        const int li0 = ((d0 & 7) << 2) | ((n & 7) >> 1);
                        const int a0 = ((((h * 4 + (n >> 4)) * 4 + (d0 >> 3)) * 32 + li0) * 2 + reg) * 4 + (n & 1) * 2;
                        *(__nv_bfloat16*)(sm + OFF_VFH + a0) = hi0;
                        *(__nv_bfloat16*)(sm + OFF_VFL + a0) = lo0;
                        const int d1 = d0 + 1;
                        const int li1 = ((d1 & 7) << 2) | ((n & 7) >> 1);
                        const int a1 = ((((h * 4 + (n >> 4)) * 4 + (d1 >> 3)) * 32 + li1) * 2 + reg) * 4 + (n & 1) * 2;
                        *(__nv_bfloat16*)(sm + OFF_VFH + a1) = hi1;
                        *(__nv_bfloat16*)(sm + OFF_VFL + a1) = lo1;
                    }
                }
            }
        }
    }
    __syncthreads();

    // ---- phase 2: attention, one (head, 16-row tile) per warp ----
    {
        const int h = wid >> 2, mt = wid & 3;
        const int r0 = mt * 16 + g, r1 = r0 + 8;

        // q A-frags
        uint4 ah[2], al[2];
        #pragma unroll
        for (int kc = 0; kc < 2; kc++) {
            const int idx = (((h * 4 + mt) * 2 + kc) * 32 + lane) << 4;
            ah[kc] = *(const uint4*)(sm + OFF_QFH + idx);
            al[kc] = *(const uint4*)(sm + OFF_QFL + idx);
        }

        // S = q k^T  (7 n-tiles of 8 keys)
        float c[7][4];
        #pragma unroll
        for (int nt = 0; nt < 7; nt++)
            #pragma unroll
            for (int e = 0; e < 4; e++) c[nt][e] = 0.f;

        #pragma unroll
        for (int nt = 0; nt < 7; nt++)
            #pragma unroll
            for (int kc = 0; kc < 2; kc++) {
                const int idx = (((h * 7 + nt) * 2 + kc) * 32 + lane) << 3;
                const uint2 bh = *(const uint2*)(sm + OFF_KFH + idx);
                const uint2 bl = *(const uint2*)(sm + OFF_KFL + idx);
                mma16816(c[nt], (const uint32_t*)&ah[kc], (const uint32_t*)&bh);
                mma16816(c[nt], (const uint32_t*)&ah[kc], (const uint32_t*)&bl);
                mma16816(c[nt], (const uint32_t*)&al[kc], (const uint32_t*)&bh);
            }

        // bias + mask in c-frag layout
        #pragma unroll
        for (int nt = 0; nt < 7; nt++)
            #pragma unroll
            for (int e = 0; e < 4; e++) {
                const int r = (e >= 2) ? r1 : r0;
                const int m = nt * 8 + tq * 2 + (e & 1);
                if (m < N_TOK && r < N_TOK)
                    c[nt][e] += rel_s[(int)ridx_s[r * 49 + m] * NHEADS + h] + mask_s[r * 49 + m];
                else
                    c[nt][e] = -1e30f;
            }

        // softmax: rows r0 (e=0,1) and r1 (e=2,3); reduce across 4-lane group
        float mx0 = -1e30f, mx1 = -1e30f;
        #pragma unroll
        for (int nt = 0; nt < 7; nt++) {
            mx0 = fmaxf(mx0, fmaxf(c[nt][0], c[nt][1]));
            mx1 = fmaxf(mx1, fmaxf(c[nt][2], c[nt][3]));
        }
        mx0 = fmaxf(mx0, __shfl_xor_sync(~0u, mx0, 1));
        mx0 = fmaxf(mx0, __shfl_xor_sync(~0u, mx0, 2));
        mx1 = fmaxf(mx1, __shfl_xor_sync(~0u, mx1, 1));
        mx1 = fmaxf(mx1, __shfl_xor_sync(~0u, mx1, 2));
        float s0 = 0.f, s1 = 0.f;
        #pragma unroll
        for (int nt = 0; nt < 7; nt++) {
            c[nt][0] = __expf(c[nt][0] - mx0); s0 += c[nt][0];
            c[nt][1] = __expf(c[nt][1] - mx0); s0 += c[nt][1];
            c[nt][2] = __expf(c[nt][2] - mx1); s1 += c[nt][2];
            c[nt][3] = __expf(c[nt][3] - mx1); s1 += c[nt][3];
        }
        s0 += __shfl_xor_sync(~0u, s0, 1);
        s0 += __shfl_xor_sync(~0u, s0, 2);
        s1 += __shfl_xor_sync(~0u, s1, 1);
        s1 += __shfl_xor_sync(~0u, s1, 2);
        const float inv0 = 1.f / s0, inv1 = 1.f / s1;
        #pragma unroll
        for (int nt = 0; nt < 7; nt++) {
            c[nt][0] *= inv0; c[nt][1] *= inv0;
            c[nt][2] *= inv1; c[nt][3] *= inv1;
        }

        // PV: P (c-frags -> A-frags in registers) x V (B-frags)
        float o_[4][4];
        #pragma unroll
        for (int nd = 0; nd < 4; nd++)
            #pragma unroll
            for (int e = 0; e < 4; e++) o_[nd][e] = 0.f;

        #pragma unroll
        for (int kck = 0; kck < 4; kck++) {
            uint32_t pah[4], pal[4];
            pack_hl(c[2 * kck][0],     c[2 * kck][1],     pah[0], pal[0]);
            pack_hl(c[2 * kck][2],     c[2 * kck][3],     pah[1], pal[1]);
            pack_hl(c[2 * kck + 1][0], c[2 * kck + 1][1], pah[2], pal[2]);
            pack_hl(c[2 * kck + 1][2], c[2 * kck + 1][3], pah[3], pal[3]);
            #pragma unroll
            for (int nd = 0; nd < 4; nd++) {
                const int idx = (((h * 4 + kck) * 4 + nd) * 32 + lane) << 3;
                const uint2 vh = *(const uint2*)(sm + OFF_VFH + idx);
                const uint2 vl = *(const uint2*)(sm + OFF_VFL + idx);
                mma16816(o_[nd], pah, (const uint32_t*)&vh);
                mma16816(o_[nd], pah, (const uint32_t*)&vl);
                mma16816(o_[nd], pal, (const uint32_t*)&vh);
            }
        }

        // writeback
        float* ob = out + (size_t)b * 6272 + h * 32;
        #pragma unroll
        for (int nd = 0; nd < 4; nd++) {
            const int d0 = nd * 8 + tq * 2;
            if (r0 < N_TOK)
                *(float2*)(ob + r0 * 128 + d0) = make_float2(o_[nd][0], o_[nd][1]);
            if (r1 < N_TOK)
                *(float2*)(ob + r1 * 128 + d0) = make_float2(o_[nd][2], o_[nd][3]);
        }
    }
}

extern "C" void kernel_launch(void* const* d_in, const int* in_sizes, int n_in,
                              void* d_out, int out_size)
{
    const float* x    = (const float*)d_in[0];
    const float* mask = (const float*)d_in[1];
    const float* W    = (const float*)d_in[2];
    const float* bvec = (const float*)d_in[3];
    const float* rel  = (const float*)d_in[4];
    float* out = (float*)d_out;

    prep_w<<<96, 256>>>(W);
    cudaFuncSetAttribute(win_attn_kernel,
                         cudaFuncAttributeMaxDynamicSharedMemorySize, SMEM_TOTAL);
    win_attn_kernel<<<4096, THREADS, SMEM_TOTAL>>>(x, mask, bvec, rel, out);
}

// round 13
// speedup vs baseline: 1.3687x; 1.1173x over previous
#include <cuda_runtime.h>
#include <cuda_bf16.h>
#include <cstdint>

#define N_TOK   49
#define NHEADS  4
#define NWIN    64
#define THREADS 512

// ---- smem byte offsets ----
#define OFF_XH   0          // 16384
#define OFF_XL   16384      // 16384
#define OFF_QFH  32768      // 16384  q A-frags hi  [h][mt4][kc2][lane][reg4] u32
#define OFF_QFL  49152      // 16384
#define OFF_KFH  65536      // 14336  k B-frags hi  [h][nt7][kc2][lane][reg2] u32
#define OFF_KFL  79872      // 14336
#define OFF_VFH  94208      // 16384  v B-frags hi  [h][kck4][ntd4][lane][reg2] u32
#define OFF_VFL  110592     // 16384
#define OFF_BVEC 126976     // 384 f32 (PERMUTED order o' = which*128 + h*32 + d)
#define SMEM_TOTAL 128512

// W in fragment layout with PERMUTED columns: o' = which*128 + h*32 + d
// [c8(48)][kc(8)][lane(32)][reg(2)] u32 (bf16 pairs)
__device__ __align__(16) uint32_t g_wfh[48 * 8 * 32 * 2];
__device__ __align__(16) uint32_t g_wfl[48 * 8 * 32 * 2];
// fused bias+mask: [win(64)][h(4)][r(49)*49+m] f32
__device__ __align__(16) float g_bm[NWIN * NHEADS * 2401];

__device__ __forceinline__ void mma16816(float* c, const uint32_t* a, const uint32_t* b) {
    asm volatile(
        "mma.sync.aligned.m16n8k16.row.col.f32.bf16.bf16.f32 "
        "{%0,%1,%2,%3}, {%4,%5,%6,%7}, {%8,%9}, {%0,%1,%2,%3};"
        : "+f"(c[0]), "+f"(c[1]), "+f"(c[2]), "+f"(c[3])
        : "r"(a[0]), "r"(a[1]), "r"(a[2]), "r"(a[3]), "r"(b[0]), "r"(b[1]));
}

__device__ __forceinline__ void split_bf16(float v, __nv_bfloat16& h, __nv_bfloat16& l) {
    h = __float2bfloat16(v);
    l = __float2bfloat16(v - __bfloat162float(h));
}

__device__ __forceinline__ void pack_hl(float a, float b, uint32_t& ph, uint32_t& pl) {
    __nv_bfloat16 ha, la, hb, lb;
    split_bf16(a, ha, la);
    split_bf16(b, hb, lb);
    ph = (uint32_t)__bfloat16_as_ushort(ha) | ((uint32_t)__bfloat16_as_ushort(hb) << 16);
    pl = (uint32_t)__bfloat16_as_ushort(la) | ((uint32_t)__bfloat16_as_ushort(lb) << 16);
}

__device__ __forceinline__ int permute_col(int o) {
    // torch split order o = h*96 + d*3 + which  ->  o' = which*128 + h*32 + d
    const int h = o / 96, rem = o - 96 * h;
    const int d = rem / 3, which = rem - 3 * d;
    return which * 128 + h * 32 + d;
}

// ---- prep: W (384x128 f32) -> bf16 hi/lo fragment tiles, column-permuted ----
__global__ void prep_w(const float* __restrict__ W) {
    for (int i = blockIdx.x * blockDim.x + threadIdx.x; i < 384 * 64;
         i += gridDim.x * blockDim.x) {
        const int o = i >> 6, kp = i & 63, k = kp * 2;
        const float w0 = W[o * 128 + k], w1 = W[o * 128 + k + 1];
        __nv_bfloat16 h0, l0, h1, l1;
        split_bf16(w0, h0, l0);
        split_bf16(w1, h1, l1);
        const uint32_t ph = (uint32_t)__bfloat16_as_ushort(h0)
                          | ((uint32_t)__bfloat16_as_ushort(h1) << 16);
        const uint32_t pl = (uint32_t)__bfloat16_as_ushort(l0)
                          | ((uint32_t)__bfloat16_as_ushort(l1) << 16);
        const int op = permute_col(o);
        const int c8 = op >> 3, g = op & 7, kc = k >> 4, kk = k & 15;
        const int reg = (kk >= 8), j = (kk & 7) >> 1;
        const int pos = (((c8 * 8 + kc) * 32) + g * 4 + j) * 2 + reg;
        g_wfh[pos] = ph;
        g_wfl[pos] = pl;
    }
}

// ---- prep: fused bias+mask table g_bm[win][h][r*49+m] ----
__global__ void prep_bm(const float* __restrict__ mask,
                        const float* __restrict__ rel_table) {
    for (int i = blockIdx.x * blockDim.x + threadIdx.x; i < NWIN * NHEADS * 2401;
         i += gridDim.x * blockDim.x) {
        const int w = i / (NHEADS * 2401), rem = i - w * (NHEADS * 2401);
        const int h = rem / 2401, j = rem - h * 2401;
        const int r = j / 49, m = j - r * 49;
        const int ridx = (r / 7 - m / 7 + 6) * 13 + (r % 7 - m % 7 + 6);
        g_bm[i] = __ldg(&rel_table[ridx * NHEADS + h]) + __ldg(&mask[w * 2401 + j]);
    }
}

__global__ __launch_bounds__(THREADS, 1)
void win_attn_kernel(const float* __restrict__ x,
                     const float* __restrict__ bvec,
                     float* __restrict__ out)
{
    extern __shared__ char sm[];
    float* bvec_s = (float*)(sm + OFF_BVEC);

    const int t = threadIdx.x, wid = t >> 5, lane = t & 31;
    const int g = lane >> 2, tq = lane & 3;
    const int b = blockIdx.x;

    // ---- phase 0: zero v-frags, stage bvec (permuted) + x frags ----
    {
        uint4 z = make_uint4(0, 0, 0, 0);
        uint4* v4 = (uint4*)(sm + OFF_VFH);
        for (int i = t; i < 2048; i += THREADS) v4[i] = z;  // VFH + VFL (32KB)
    }
    for (int i = t; i < 384; i += THREADS) bvec_s[permute_col(i)] = bvec[i];
    {
        const float4* xg = (const float4*)(x + (size_t)b * 6272);
        uint32_t* xh = (uint32_t*)(sm + OFF_XH);
        uint32_t* xl = (uint32_t*)(sm + OFF_XL);
        for (int i = t; i < 64 * 32; i += THREADS) {
            const int r = i >> 5, k0 = (i & 31) * 4;
            float4 v = make_float4(0.f, 0.f, 0.f, 0.f);
            if (r < N_TOK) v = xg[r * 32 + (i & 31)];
            __nv_bfloat16 h0, l0, h1, l1, h2, l2, h3, l3;
            split_bf16(v.x, h0, l0); split_bf16(v.y, h1, l1);
            split_bf16(v.z, h2, l2); split_bf16(v.w, h3, l3);
            const uint32_t ph01 = (uint32_t)__bfloat16_as_ushort(h0) | ((uint32_t)__bfloat16_as_ushort(h1) << 16);
            const uint32_t ph23 = (uint32_t)__bfloat16_as_ushort(h2) | ((uint32_t)__bfloat16_as_ushort(h3) << 16);
            const uint32_t pl01 = (uint32_t)__bfloat16_as_ushort(l0) | ((uint32_t)__bfloat16_as_ushort(l1) << 16);
            const uint32_t pl23 = (uint32_t)__bfloat16_as_ushort(l2) | ((uint32_t)__bfloat16_as_ushort(l3) << 16);
            const int mt = r >> 4, r16 = r & 15, g8 = r16 & 7;
            const int kc = k0 >> 4, kk = k0 & 15;
            const int reg = (r16 >= 8 ? 1 : 0) + (kk >= 8 ? 2 : 0);
            const int jj = (kk & 7) >> 1;
            const int base = (((mt * 8 + kc) * 32) + g8 * 4 + jj) * 4 + reg;
            xh[base] = ph01; xh[base + 4] = ph23;
            xl[base] = pl01; xl[base + 4] = pl23;
        }
    }
    __syncthreads();

    // ---- phase 1: projection, one 64x24 warp tile per warp ----
    {
        float c[4][3][4];
        #pragma unroll
        for (int mt = 0; mt < 4; mt++)
            #pragma unroll
            for (int j = 0; j < 3; j++)
                #pragma unroll
                for (int e = 0; e < 4; e++) c[mt][j][e] = 0.f;

        const uint2* wfh = (const uint2*)g_wfh;
        const uint2* wfl = (const uint2*)g_wfl;
        #pragma unroll
        for (int kc = 0; kc < 8; kc++) {
            uint4 ah[4], al[4];
            #pragma unroll
            for (int mt = 0; mt < 4; mt++) {
                const int idx = (((mt * 8 + kc) * 32) + lane) << 4;
                ah[mt] = *(const uint4*)(sm + OFF_XH + idx);
                al[mt] = *(const uint4*)(sm + OFF_XL + idx);
            }
            uint2 bh[3], bl[3];
            #pragma unroll
            for (int j = 0; j < 3; j++) {
                const int idx = ((wid * 3 + j) * 8 + kc) * 32 + lane;
                bh[j] = __ldg(&wfh[idx]);
                bl[j] = __ldg(&wfl[idx]);
            }
            #pragma unroll
            for (int mt = 0; mt < 4; mt++)
                #pragma unroll
                for (int j = 0; j < 3; j++) {
                    mma16816(c[mt][j], (const uint32_t*)&ah[mt], (const uint32_t*)&bh[j]);
                    mma16816(c[mt][j], (const uint32_t*)&ah[mt], (const uint32_t*)&bl[j]);
                    mma16816(c[mt][j], (const uint32_t*)&al[mt], (const uint32_t*)&bh[j]);
                }
        }

        // epilogue (permuted columns): per j-tile a single which/h; (e,e+1) = (d,d+1) u32 granule
        const float scale = 0.17677669529663687f;  // 1/sqrt(32), folded into q
        #pragma unroll
        for (int j = 0; j < 3; j++) {
            const int ocol  = wid * 24 + j * 8 + tq * 2;  // even permuted col
            const int which = ocol >> 7;
            const int h     = (ocol >> 5) & 3;
            const int d0    = ocol & 31;
            const float b0 = bvec_s[ocol], b1 = bvec_s[ocol + 1];
            #pragma unroll
            for (int mt = 0; mt < 4; mt++) {
                #pragma unroll
                for (int half = 0; half < 2; half++) {
                    const int n = mt * 16 + g + half * 8;
                    if (n >= N_TOK) continue;
                    float v0 = c[mt][j][half * 2 + 0] + b0;
                    float v1 = c[mt][j][half * 2 + 1] + b1;
                    if (which == 0) { v0 *= scale; v1 *= scale; }
                    if (which == 0) {        // q A-frag: one u32 (hi) + one u32 (lo)
                        uint32_t ph, pl;
                        pack_hl(v0, v1, ph, pl);
                        const int li = ((n & 7) << 2) | ((d0 & 7) >> 1);
                        const int reg = ((n & 15) >= 8 ? 1 : 0) + ((d0 & 15) >= 8 ? 2 : 0);
                        const int addr = ((((h * 4 + (n >> 4)) * 2 + (d0 >> 4)) * 32 + li) * 4 + reg) * 4;
                        *(uint32_t*)(sm + OFF_QFH + addr) = ph;
                        *(uint32_t*)(sm + OFF_QFL + addr) = pl;
                    } else if (which == 1) { // k B-frag: one u32 + one u32
                        uint32_t ph, pl;
                        pack_hl(v0, v1, ph, pl);
                        const int li = ((n & 7) << 2) | ((d0 & 7) >> 1);
                        const int reg = ((d0 & 15) >= 8 ? 1 : 0);
                        const int addr = ((((h * 7 + (n >> 3)) * 2 + (d0 >> 4)) * 32 + li) * 2 + reg) * 4;
                        *(uint32_t*)(sm + OFF_KFH + addr) = ph;
                        *(uint32_t*)(sm + OFF_KFL + addr) = pl;
                    } else {                 // v B-frag: granule pairs over n -> 2x bf16 stores
                        __nv_bfloat16 hi0, lo0, hi1, lo1;
                        split_bf16(v0, hi0, lo0);
                        split_bf16(v1, hi1, lo1);
                        const int reg = ((n & 15) >= 8 ? 1 : 0);
                        const int li0 = ((d0 & 7) << 2) | ((n & 7) >> 1);
                        const int a0 = ((((h * 4 + (n >> 4)) * 4 + (d0 >> 3)) * 32 + li0) * 2 + reg) * 4 + (n & 1) * 2;
                        *(__nv_bfloat16*)(sm + OFF_VFH + a0) = hi0;
                        *(__nv_bfloat16*)(sm + OFF_VFL + a0) = lo0;
                        const int d1 = d0 + 1;
                        const int li1 = ((d1 & 7) << 2) | ((n & 7) >> 1);
                        const int a1 = ((((h * 4 + (n >> 4)) * 4 + (d1 >> 3)) * 32 + li1) * 2 + reg) * 4 + (n & 1) * 2;
                        *(__nv_bfloat16*)(sm + OFF_VFH + a1) = hi1;
                        *(__nv_bfloat16*)(sm + OFF_VFL + a1) = lo1;
                    }
                }
            }
        }
    }
    __syncthreads();

    // ---- phase 2: attention, one (head, 16-row tile) per warp ----
    {
        const int h = wid >> 2, mt = wid & 3;
        const int r0 = mt * 16 + g, r1 = r0 + 8;
        const float* bmg = g_bm + ((size_t)(b & (NWIN - 1)) * NHEADS + h) * 2401;

        // q A-frags
        uint4 ah[2], al[2];
        #pragma unroll
        for (int kc = 0; kc < 2; kc++) {
            const int idx = (((h * 4 + mt) * 2 + kc) * 32 + lane) << 4;
            ah[kc] = *(const uint4*)(sm + OFF_QFH + idx);
            al[kc] = *(const uint4*)(sm + OFF_QFL + idx);
        }

        // S = q k^T  (7 n-tiles of 8 keys)
        float c[7][4];
        #pragma unroll
        for (int nt = 0; nt < 7; nt++)
            #pragma unroll
            for (int e = 0; e < 4; e++) c[nt][e] = 0.f;

        #pragma unroll
        for (int nt = 0; nt < 7; nt++)
            #pragma unroll
            for (int kc = 0; kc < 2; kc++) {
                const int idx = (((h * 7 + nt) * 2 + kc) * 32 + lane) << 3;
                const uint2 bh = *(const uint2*)(sm + OFF_KFH + idx);
                const uint2 bl = *(const uint2*)(sm + OFF_KFL + idx);
                mma16816(c[nt], (const uint32_t*)&ah[kc], (const uint32_t*)&bh);
                mma16816(c[nt], (const uint32_t*)&ah[kc], (const uint32_t*)&bl);
                mma16816(c[nt], (const uint32_t*)&al[kc], (const uint32_t*)&bh);
            }

        // fused bias+mask (L2-resident global table) in c-frag layout
        #pragma unroll
        for (int nt = 0; nt < 7; nt++)
            #pragma unroll
            for (int e = 0; e < 4; e++) {
                const int r = (e >= 2) ? r1 : r0;
                const int m = nt * 8 + tq * 2 + (e & 1);
                if (m < N_TOK && r < N_TOK)
                    c[nt][e] += __ldg(&bmg[r * 49 + m]);
                else
                    c[nt][e] = -1e30f;
            }

        // softmax: rows r0 (e=0,1) and r1 (e=2,3); reduce across 4-lane group
        float mx0 = -1e30f, mx1 = -1e30f;
        #pragma unroll
        for (int nt = 0; nt < 7; nt++) {
            mx0 = fmaxf(mx0, fmaxf(c[nt][0], c[nt][1]));
            mx1 = fmaxf(mx1, fmaxf(c[nt][2], c[nt][3]));
        }
        mx0 = fmaxf(mx0, __shfl_xor_sync(~0u, mx0, 1));
        mx0 = fmaxf(mx0, __shfl_xor_sync(~0u, mx0, 2));
        mx1 = fmaxf(mx1, __shfl_xor_sync(~0u, mx1, 1));
        mx1 = fmaxf(mx1, __shfl_xor_sync(~0u, mx1, 2));
        float s0 = 0.f, s1 = 0.f;
        #pragma unroll
        for (int nt = 0; nt < 7; nt++) {
            c[nt][0] = __expf(c[nt][0] - mx0); s0 += c[nt][0];
            c[nt][1] = __expf(c[nt][1] - mx0); s0 += c[nt][1];
            c[nt][2] = __expf(c[nt][2] - mx1); s1 += c[nt][2];
            c[nt][3] = __expf(c[nt][3] - mx1); s1 += c[nt][3];
        }
        s0 += __shfl_xor_sync(~0u, s0, 1);
        s0 += __shfl_xor_sync(~0u, s0, 2);
        s1 += __shfl_xor_sync(~0u, s1, 1);
        s1 += __shfl_xor_sync(~0u, s1, 2);
        const float inv0 = 1.f / s0, inv1 = 1.f / s1;
        #pragma unroll
        for (int nt = 0; nt < 7; nt++) {
            c[nt][0] *= inv0; c[nt][1] *= inv0;
            c[nt][2] *= inv1; c[nt][3] *= inv1;
        }

        // PV: P (c-frags -> A-frags in registers) x V (B-frags)
        float o_[4][4];
        #pragma unroll
        for (int nd = 0; nd < 4; nd++)
            #pragma unroll
            for (int e = 0; e < 4; e++) o_[nd][e] = 0.f;

        #pragma unroll
        for (int kck = 0; kck < 4; kck++) {
            uint32_t pah[4], pal[4];
            pack_hl(c[2 * kck][0],     c[2 * kck][1],     pah[0], pal[0]);
            pack_hl(c[2 * kck][2],     c[2 * kck][3],     pah[1], pal[1]);
            pack_hl(c[2 * kck + 1][0], c[2 * kck + 1][1], pah[2], pal[2]);
            pack_hl(c[2 * kck + 1][2], c[2 * kck + 1][3], pah[3], pal[3]);
            #pragma unroll
            for (int nd = 0; nd < 4; nd++) {
                const int idx = (((h * 4 + kck) * 4 + nd) * 32 + lane) << 3;
                const uint2 vh = *(const uint2*)(sm + OFF_VFH + idx);
                const uint2 vl = *(const uint2*)(sm + OFF_VFL + idx);
                mma16816(o_[nd], pah, (const uint32_t*)&vh);
                mma16816(o_[nd], pah, (const uint32_t*)&vl);
                mma16816(o_[nd], pal, (const uint32_t*)&vh);
            }
        }

        // writeback
        float* ob = out + (size_t)b * 6272 + h * 32;
        #pragma unroll
        for (int nd = 0; nd < 4; nd++) {
            const int d0 = nd * 8 + tq * 2;
            if (r0 < N_TOK)
                *(float2*)(ob + r0 * 128 + d0) = make_float2(o_[nd][0], o_[nd][1]);
            if (r1 < N_TOK)
                *(float2*)(ob + r1 * 128 + d0) = make_float2(o_[nd][2], o_[nd][3]);
        }
    }
}

extern "C" void kernel_launch(void* const* d_in, const int* in_sizes, int n_in,
                              void* d_out, int out_size)
{
    const float* x    = (const float*)d_in[0];
    const float* mask = (const float*)d_in[1];
    const float* W    = (const float*)d_in[2];
    const float* bvec = (const float*)d_in[3];
    const float* rel  = (const float*)d_in[4];
    float* out = (float*)d_out;

    prep_w<<<96, 256>>>(W);
    prep_bm<<<512, 256>>>(mask, rel);
    cudaFuncSetAttribute(win_attn_kernel,
                         cudaFuncAttributeMaxDynamicSharedMemorySize, SMEM_TOTAL);
    win_attn_kernel<<<4096, THREADS, SMEM_TOTAL>>>(x, bvec, out);
}

// round 14
// speedup vs baseline: 1.7321x; 1.2655x over previous
#include <cuda_runtime.h>
#include <cuda_bf16.h>
#include <cstdint>

#define N_TOK   49
#define NHEADS  4
#define NWIN    64
#define THREADS 384

// ---- smem byte offsets (93.5 KB -> 2 CTAs/SM) ----
// VF aliases XH/XL (x frags dead by the time VF is written; deferred v epilogue)
#define OFF_XH   0          // 16384
#define OFF_XL   16384      // 16384
#define OFF_VFH  0          // 16384 (alias XH)
#define OFF_VFL  16384      // 16384 (alias XL)
#define OFF_QFH  32768      // 16384  q A-frags hi  [h][mt4][kc2][lane][reg4] u32
#define OFF_QFL  49152      // 16384
#define OFF_KFH  65536      // 14336  k B-frags hi  [h][nt7][kc2][lane][reg2] u32
#define OFF_KFL  79872      // 14336
#define OFF_BVEC 94208      // 384 f32 (PERMUTED order o' = which*128 + h*32 + d)
#define SMEM_TOTAL 95744

// W in fragment layout with PERMUTED columns: o' = which*128 + h*32 + d
// [c8(48)][kc(8)][lane(32)][reg(2)] u32 (bf16 pairs)
__device__ __align__(16) uint32_t g_wfh[48 * 8 * 32 * 2];
__device__ __align__(16) uint32_t g_wfl[48 * 8 * 32 * 2];
// fused bias+mask: [win(64)][h(4)][r(49)*49+m] f32
__device__ __align__(16) float g_bm[NWIN * NHEADS * 2401];

__device__ __forceinline__ void mma16816(float* c, const uint32_t* a, const uint32_t* b) {
    asm volatile(
        "mma.sync.aligned.m16n8k16.row.col.f32.bf16.bf16.f32 "
        "{%0,%1,%2,%3}, {%4,%5,%6,%7}, {%8,%9}, {%0,%1,%2,%3};"
        : "+f"(c[0]), "+f"(c[1]), "+f"(c[2]), "+f"(c[3])
        : "r"(a[0]), "r"(a[1]), "r"(a[2]), "r"(a[3]), "r"(b[0]), "r"(b[1]));
}

__device__ __forceinline__ void split_bf16(float v, __nv_bfloat16& h, __nv_bfloat16& l) {
    h = __float2bfloat16(v);
    l = __float2bfloat16(v - __bfloat162float(h));
}

__device__ __forceinline__ void pack_hl(float a, float b, uint32_t& ph, uint32_t& pl) {
    __nv_bfloat16 ha, la, hb, lb;
    split_bf16(a, ha, la);
    split_bf16(b, hb, lb);
    ph = (uint32_t)__bfloat16_as_ushort(ha) | ((uint32_t)__bfloat16_as_ushort(hb) << 16);
    pl = (uint32_t)__bfloat16_as_ushort(la) | ((uint32_t)__bfloat16_as_ushort(lb) << 16);
}

__device__ __forceinline__ int permute_col(int o) {
    // torch split order o = h*96 + d*3 + which  ->  o' = which*128 + h*32 + d
    const int h = o / 96, rem = o - 96 * h;
    const int d = rem / 3, which = rem - 3 * d;
    return which * 128 + h * 32 + d;
}

// ---- prep: W (384x128 f32) -> bf16 hi/lo fragment tiles, column-permuted ----
__global__ void prep_w(const float* __restrict__ W) {
    for (int i = blockIdx.x * blockDim.x + threadIdx.x; i < 384 * 64;
         i += gridDim.x * blockDim.x) {
        const int o = i >> 6, kp = i & 63, k = kp * 2;
        const float w0 = W[o * 128 + k], w1 = W[o * 128 + k + 1];
        __nv_bfloat16 h0, l0, h1, l1;
        split_bf16(w0, h0, l0);
        split_bf16(w1, h1, l1);
        const uint32_t ph = (uint32_t)__bfloat16_as_ushort(h0)
                          | ((uint32_t)__bfloat16_as_ushort(h1) << 16);
        const uint32_t pl = (uint32_t)__bfloat16_as_ushort(l0)
                          | ((uint32_t)__bfloat16_as_ushort(l1) << 16);
        const int op = permute_col(o);
        const int c8 = op >> 3, g = op & 7, kc = k >> 4, kk = k & 15;
        const int reg = (kk >= 8), j = (kk & 7) >> 1;
        const int pos = (((c8 * 8 + kc) * 32) + g * 4 + j) * 2 + reg;
        g_wfh[pos] = ph;
        g_wfl[pos] = pl;
    }
}

// ---- prep: fused bias+mask table g_bm[win][h][r*49+m] ----
__global__ void prep_bm(const float* __restrict__ mask,
                        const float* __restrict__ rel_table) {
    for (int i = blockIdx.x * blockDim.x + threadIdx.x; i < NWIN * NHEADS * 2401;
         i += gridDim.x * blockDim.x) {
        const int w = i / (NHEADS * 2401), rem = i - w * (NHEADS * 2401);
        const int h = rem / 2401, j = rem - h * 2401;
        const int r = j / 49, m = j - r * 49;
        const int ridx = (r / 7 - m / 7 + 6) * 13 + (r % 7 - m % 7 + 6);
        g_bm[i] = __ldg(&rel_table[ridx * NHEADS + h]) + __ldg(&mask[w * 2401 + j]);
    }
}

// epilogue writer for one 16-col tile (2 j-groups of 8 cols)
__device__ __forceinline__ void write_epilogue(char* sm, int tile, int g, int tq,
                                               float c[2][4][4], const float* bvec_s) {
    const float scale = 0.17677669529663687f;  // 1/sqrt(32), folded into q
    const int which = (tile * 16) >> 7;
    const int h     = ((tile * 16) >> 5) & 3;
    #pragma unroll
    for (int j = 0; j < 2; j++) {
        const int ocol = tile * 16 + j * 8 + tq * 2;
        const int d0   = ocol & 31;
        const float b0 = bvec_s[ocol], b1 = bvec_s[ocol + 1];
        #pragma unroll
        for (int mt = 0; mt < 4; mt++) {
            #pragma unroll
            for (int half = 0; half < 2; half++) {
                const int n = mt * 16 + g + half * 8;
                if (n >= N_TOK) continue;
                float v0 = c[j][mt][half * 2 + 0] + b0;
                float v1 = c[j][mt][half * 2 + 1] + b1;
                if (which == 0) { v0 *= scale; v1 *= scale; }
                if (which == 0) {        // q A-frag
                    uint32_t ph, pl;
                    pack_hl(v0, v1, ph, pl);
                    const int li = ((n & 7) << 2) | ((d0 & 7) >> 1);
                    const int reg = ((n & 15) >= 8 ? 1 : 0) + ((d0 & 15) >= 8 ? 2 : 0);
                    const int addr = ((((h * 4 + (n >> 4)) * 2 + (d0 >> 4)) * 32 + li) * 4 + reg) * 4;
                    *(uint32_t*)(sm + OFF_QFH + addr) = ph;
                    *(uint32_t*)(sm + OFF_QFL + addr) = pl;
                } else if (which == 1) { // k B-frag
                    uint32_t ph, pl;
                    pack_hl(v0, v1, ph, pl);
                    const int li = ((n & 7) << 2) | ((d0 & 7) >> 1);
                    const int reg = ((d0 & 15) >= 8 ? 1 : 0);
                    const int addr = ((((h * 7 + (n >> 3)) * 2 + (d0 >> 4)) * 32 + li) * 2 + reg) * 4;
                    *(uint32_t*)(sm + OFF_KFH + addr) = ph;
                    *(uint32_t*)(sm + OFF_KFL + addr) = pl;
                } else {                 // v B-frag (granule pairs over n)
                    __nv_bfloat16 hi0, lo0, hi1, lo1;
                    split_bf16(v0, hi0, lo0);
                    split_bf16(v1, hi1, lo1);
                    const int reg = ((n & 15) >= 8 ? 1 : 0);
                    const int li0 = ((d0 & 7) << 2) | ((n & 7) >> 1);
                    const int a0 = ((((h * 4 + (n >> 4)) * 4 + (d0 >> 3)) * 32 + li0) * 2 + reg) * 4 + (n & 1) * 2;
                    *(__nv_bfloat16*)(sm + OFF_VFH + a0) = hi0;
                    *(__nv_bfloat16*)(sm + OFF_VFL + a0) = lo0;
                    const int d1 = d0 + 1;
                    const int li1 = ((d1 & 7) << 2) | ((n & 7) >> 1);
                    const int a1 = ((((h * 4 + (n >> 4)) * 4 + (d1 >> 3)) * 32 + li1) * 2 + reg) * 4 + (n & 1) * 2;
                    *(__nv_bfloat16*)(sm + OFF_VFH + a1) = hi1;
                    *(__nv_bfloat16*)(sm + OFF_VFL + a1) = lo1;
                }
            }
        }
    }
}

__device__ __forceinline__ void proj_tile(char* sm, int tile, int lane,
                                          float c[2][4][4]) {
    #pragma unroll
    for (int j = 0; j < 2; j++)
        #pragma unroll
        for (int mt = 0; mt < 4; mt++)
            #pragma unroll
            for (int e = 0; e < 4; e++) c[j][mt][e] = 0.f;

    const uint2* wfh = (const uint2*)g_wfh;
    const uint2* wfl = (const uint2*)g_wfl;
    #pragma unroll
    for (int kc = 0; kc < 8; kc++) {
        uint4 ah[4], al[4];
        #pragma unroll
        for (int mt = 0; mt < 4; mt++) {
            const int idx = (((mt * 8 + kc) * 32) + lane) << 4;
            ah[mt] = *(const uint4*)(sm + OFF_XH + idx);
            al[mt] = *(const uint4*)(sm + OFF_XL + idx);
        }
        uint2 bh[2], bl[2];
        #pragma unroll
        for (int j = 0; j < 2; j++) {
            const int idx = ((tile * 2 + j) * 8 + kc) * 32 + lane;
            bh[j] = __ldg(&wfh[idx]);
            bl[j] = __ldg(&wfl[idx]);
        }
        #pragma unroll
        for (int j = 0; j < 2; j++)
            #pragma unroll
            for (int mt = 0; mt < 4; mt++) {
                mma16816(c[j][mt], (const uint32_t*)&ah[mt], (const uint32_t*)&bh[j]);
                mma16816(c[j][mt], (const uint32_t*)&ah[mt], (const uint32_t*)&bl[j]);
                mma16816(c[j][mt], (const uint32_t*)&al[mt], (const uint32_t*)&bh[j]);
            }
    }
}

__global__ __launch_bounds__(THREADS, 2)
void win_attn_kernel(const float* __restrict__ x,
                     const float* __restrict__ bvec,
                     float* __restrict__ out)
{
    extern __shared__ char sm[];
    float* bvec_s = (float*)(sm + OFF_BVEC);

    const int t = threadIdx.x, wid = t >> 5, lane = t & 31;
    const int g = lane >> 2, tq = lane & 3;
    const int b = blockIdx.x;

    // ---- phase 0: stage bvec (permuted) + x frags (hi/lo) ----
    for (int i = t; i < 384; i += THREADS) bvec_s[permute_col(i)] = bvec[i];
    {
        const float4* xg = (const float4*)(x + (size_t)b * 6272);
        uint32_t* xh = (uint32_t*)(sm + OFF_XH);
        uint32_t* xl = (uint32_t*)(sm + OFF_XL);
        for (int i = t; i < 64 * 32; i += THREADS) {
            const int r = i >> 5, k0 = (i & 31) * 4;
            float4 v = make_float4(0.f, 0.f, 0.f, 0.f);
            if (r < N_TOK) v = xg[r * 32 + (i & 31)];
            __nv_bfloat16 h0, l0, h1, l1, h2, l2, h3, l3;
            split_bf16(v.x, h0, l0); split_bf16(v.y, h1, l1);
            split_bf16(v.z, h2, l2); split_bf16(v.w, h3, l3);
            const uint32_t ph01 = (uint32_t)__bfloat16_as_ushort(h0) | ((uint32_t)__bfloat16_as_ushort(h1) << 16);
            const uint32_t ph23 = (uint32_t)__bfloat16_as_ushort(h2) | ((uint32_t)__bfloat16_as_ushort(h3) << 16);
            const uint32_t pl01 = (uint32_t)__bfloat16_as_ushort(l0) | ((uint32_t)__bfloat16_as_ushort(l1) << 16);
            const uint32_t pl23 = (uint32_t)__bfloat16_as_ushort(l2) | ((uint32_t)__bfloat16_as_ushort(l3) << 16);
            const int mt = r >> 4, r16 = r & 15, g8 = r16 & 7;
            const int kc = k0 >> 4, kk = k0 & 15;
            const int reg = (r16 >= 8 ? 1 : 0) + (kk >= 8 ? 2 : 0);
            const int jj = (kk & 7) >> 1;
            const int base = (((mt * 8 + kc) * 32) + g8 * 4 + jj) * 4 + reg;
            xh[base] = ph01; xh[base + 4] = ph23;
            xl[base] = pl01; xl[base + 4] = pl23;
        }
    }
    __syncthreads();

    // ---- phase 1: projection, 24 tiles of 16 cols over 12 warps, 2 passes ----
    float c[2][4][4];
    // pass A: tiles 0-11 (q cols 0-127, k cols 128-191) -> immediate epilogue
    proj_tile(sm, wid, lane, c);
    write_epilogue(sm, wid, g, tq, c, bvec_s);
    // pass B: tiles 12-23; warps 0-3 -> k (immediate); warps 4-11 -> v (DEFERRED,
    // VF aliases XH/XL so writes must wait until all A-frag reads complete)
    proj_tile(sm, 12 + wid, lane, c);
    if (wid < 4) write_epilogue(sm, 12 + wid, g, tq, c, bvec_s);
    __syncthreads();                       // all A-frag reads done
    if (wid >= 4) write_epilogue(sm, 12 + wid, g, tq, c, bvec_s);
    __syncthreads();                       // q/k/v frags ready

    // ---- phase 2: attention, 16 (head, 16-row tile) tasks over 12 warps ----
    for (int task = wid; task < 16; task += 12) {
        const int h = task >> 2, mt = task & 3;
        const int r0 = mt * 16 + g, r1 = r0 + 8;
        const float* bmg = g_bm + ((size_t)(b & (NWIN - 1)) * NHEADS + h) * 2401;

        // q A-frags
        uint4 ah[2], al[2];
        #pragma unroll
        for (int kc = 0; kc < 2; kc++) {
            const int idx = (((h * 4 + mt) * 2 + kc) * 32 + lane) << 4;
            ah[kc] = *(const uint4*)(sm + OFF_QFH + idx);
            al[kc] = *(const uint4*)(sm + OFF_QFL + idx);
        }

        // S = q k^T; c2[8] covers keys 0-63 (nt=7 has no K data -> masked)
        float c2[8][4];
        #pragma unroll
        for (int nt = 0; nt < 8; nt++)
            #pragma unroll
            for (int e = 0; e < 4; e++) c2[nt][e] = 0.f;

        #pragma unroll
        for (int nt = 0; nt < 7; nt++)
            #pragma unroll
            for (int kc = 0; kc < 2; kc++) {
                const int idx = (((h * 7 + nt) * 2 + kc) * 32 + lane) << 3;
                const uint2 bh = *(const uint2*)(sm + OFF_KFH + idx);
                const uint2 bl = *(const uint2*)(sm + OFF_KFL + idx);
                mma16816(c2[nt], (const uint32_t*)&ah[kc], (const uint32_t*)&bh);
                mma16816(c2[nt], (const uint32_t*)&ah[kc], (const uint32_t*)&bl);
                mma16816(c2[nt], (const uint32_t*)&al[kc], (const uint32_t*)&bh);
            }

        // fused bias+mask (L2-resident table); mask out padding keys/rows
        #pragma unroll
        for (int nt = 0; nt < 8; nt++)
            #pragma unroll
            for (int e = 0; e < 4; e++) {
                const int r = (e >= 2) ? r1 : r0;
                const int m = nt * 8 + tq * 2 + (e & 1);
                if (m < N_TOK && r < N_TOK)
                    c2[nt][e] += __ldg(&bmg[r * 49 + m]);
                else
                    c2[nt][e] = -1e30f;
            }

        // softmax across the 4-lane group (rows r0: e=0,1; r1: e=2,3)
        float mx0 = -1e30f, mx1 = -1e30f;
        #pragma unroll
        for (int nt = 0; nt < 8; nt++) {
            mx0 = fmaxf(mx0, fmaxf(c2[nt][0], c2[nt][1]));
            mx1 = fmaxf(mx1, fmaxf(c2[nt][2], c2[nt][3]));
        }
        mx0 = fmaxf(mx0, __shfl_xor_sync(~0u, mx0, 1));
        mx0 = fmaxf(mx0, __shfl_xor_sync(~0u, mx0, 2));
        mx1 = fmaxf(mx1, __shfl_xor_sync(~0u, mx1, 1));
        mx1 = fmaxf(mx1, __shfl_xor_sync(~0u, mx1, 2));
        float s0 = 0.f, s1 = 0.f;
        #pragma unroll
        for (int nt = 0; nt < 8; nt++) {
            c2[nt][0] = __expf(c2[nt][0] - mx0); s0 += c2[nt][0];
            c2[nt][1] = __expf(c2[nt][1] - mx0); s0 += c2[nt][1];
            c2[nt][2] = __expf(c2[nt][2] - mx1); s1 += c2[nt][2];
            c2[nt][3] = __expf(c2[nt][3] - mx1); s1 += c2[nt][3];
        }
        s0 += __shfl_xor_sync(~0u, s0, 1);
        s0 += __shfl_xor_sync(~0u, s0, 2);
        s1 += __shfl_xor_sync(~0u, s1, 1);
        s1 += __shfl_xor_sync(~0u, s1, 2);
        const float inv0 = 1.f / s0, inv1 = 1.f / s1;
        #pragma unroll
        for (int nt = 0; nt < 8; nt++) {
            c2[nt][0] *= inv0; c2[nt][1] *= inv0;
            c2[nt][2] *= inv1; c2[nt][3] *= inv1;
        }

        // PV: P (c-frags -> A-frags in registers) x V (B-frags)
        float o_[4][4];
        #pragma unroll
        for (int nd = 0; nd < 4; nd++)
            #pragma unroll
            for (int e = 0; e < 4; e++) o_[nd][e] = 0.f;

        #pragma unroll
        for (int kck = 0; kck < 4; kck++) {
            uint32_t pah[4], pal[4];
            pack_hl(c2[2 * kck][0],     c2[2 * kck][1],     pah[0], pal[0]);
            pack_hl(c2[2 * kck][2],     c2[2 * kck][3],     pah[1], pal[1]);
            pack_hl(c2[2 * kck + 1][0], c2[2 * kck + 1][1], pah[2], pal[2]);
            pack_hl(c2[2 * kck + 1][2], c2[2 * kck + 1][3], pah[3], pal[3]);
            #pragma unroll
            for (int nd = 0; nd < 4; nd++) {
                const int idx = (((h * 4 + kck) * 4 + nd) * 32 + lane) << 3;
                const uint2 vh = *(const uint2*)(sm + OFF_VFH + idx);
                const uint2 vl = *(const uint2*)(sm + OFF_VFL + idx);
                mma16816(o_[nd], pah, (const uint32_t*)&vh);
                mma16816(o_[nd], pah, (const uint32_t*)&vl);
                mma16816(o_[nd], pal, (const uint32_t*)&vh);
            }
        }

        // writeback
        float* ob = out + (size_t)b * 6272 + h * 32;
        #pragma unroll
        for (int nd = 0; nd < 4; nd++) {
            const int d0 = nd * 8 + tq * 2;
            if (r0 < N_TOK)
                *(float2*)(ob + r0 * 128 + d0) = make_float2(o_[nd][0], o_[nd][1]);
            if (r1 < N_TOK)
                *(float2*)(ob + r1 * 128 + d0) = make_float2(o_[nd][2], o_[nd][3]);
        }
    }
}

extern "C" void kernel_launch(void* const* d_in, const int* in_sizes, int n_in,
                              void* d_out, int out_size)
{
    const float* x    = (const float*)d_in[0];
    const float* mask = (const float*)d_in[1];
    const float* W    = (const float*)d_in[2];
    const float* bvec = (const float*)d_in[3];
    const float* rel  = (const float*)d_in[4];
    float* out = (float*)d_out;

    prep_w<<<96, 256>>>(W);
    prep_bm<<<512, 256>>>(mask, rel);
    cudaFuncSetAttribute(win_attn_kernel,
                         cudaFuncAttributeMaxDynamicSharedMemorySize, SMEM_TOTAL);
    win_attn_kernel<<<4096, THREADS, SMEM_TOTAL>>>(x, bvec, out);
}

// round 15
// speedup vs baseline: 1.8040x; 1.0415x over previous
#include <cuda_runtime.h>
#include <cuda_bf16.h>
#include <cstdint>

#define N_TOK   49
#define NHEADS  4
#define NWIN    64
#define THREADS 384

// ---- smem byte offsets (93.5 KB -> 2 CTAs/SM) ----
// VF aliases XH/XL (x frags dead by the time VF is written; deferred v epilogue)
#define OFF_XH   0          // 16384
#define OFF_XL   16384      // 16384
#define OFF_VFH  0          // 16384 (alias XH)
#define OFF_VFL  16384      // 16384 (alias XL)
#define OFF_QFH  32768      // 16384  q A-frags hi  [h][mt4][kc2][lane][reg4] u32
#define OFF_QFL  49152      // 16384
#define OFF_KFH  65536      // 14336  k B-frags hi  [h][nt7][kc2][lane][reg2] u32
#define OFF_KFL  79872      // 14336
#define OFF_BVEC 94208      // 384 f32 (PERMUTED, q entries pre-scaled)
#define SMEM_TOTAL 95744

// W in fragment layout with PERMUTED columns: o' = which*128 + h*32 + d
// q columns pre-scaled by 1/sqrt(32). [c8(48)][kc(8)][lane(32)][reg(2)] u32
__device__ __align__(16) uint32_t g_wfh[48 * 8 * 32 * 2];
__device__ __align__(16) uint32_t g_wfl[48 * 8 * 32 * 2];
// fused bias+mask: [win(64)][h(4)][r(49)*49+m] f32
__device__ __align__(16) float g_bm[NWIN * NHEADS * 2401];

__device__ __forceinline__ void mma16816(float* c, const uint32_t* a, const uint32_t* b) {
    asm volatile(
        "mma.sync.aligned.m16n8k16.row.col.f32.bf16.bf16.f32 "
        "{%0,%1,%2,%3}, {%4,%5,%6,%7}, {%8,%9}, {%0,%1,%2,%3};"
        : "+f"(c[0]), "+f"(c[1]), "+f"(c[2]), "+f"(c[3])
        : "r"(a[0]), "r"(a[1]), "r"(a[2]), "r"(a[3]), "r"(b[0]), "r"(b[1]));
}

// pack {lo=a, hi=b} as bf16x2 in one cvt
__device__ __forceinline__ uint32_t cvt2(float a, float b) {
    uint32_t r;
    asm("cvt.rn.bf16x2.f32 %0, %1, %2;" : "=r"(r) : "f"(b), "f"(a));
    return r;
}
// exact f32 reconstruction of the bf16 halves
__device__ __forceinline__ float bf_lo(uint32_t p) { return __uint_as_float(p << 16); }
__device__ __forceinline__ float bf_hi(uint32_t p) { return __uint_as_float(p & 0xffff0000u); }

__device__ __forceinline__ void pack_hl(float a, float b, uint32_t& ph, uint32_t& pl) {
    ph = cvt2(a, b);
    pl = cvt2(a - bf_lo(ph), b - bf_hi(ph));
}

__device__ __forceinline__ int permute_col(int o) {
    // torch split order o = h*96 + d*3 + which  ->  o' = which*128 + h*32 + d
    const int h = o / 96, rem = o - 96 * h;
    const int d = rem / 3, which = rem - 3 * d;
    return which * 128 + h * 32 + d;
}

#define QSCALE 0.17677669529663687f  // 1/sqrt(32)

// ---- prep: W (384x128 f32) -> bf16 hi/lo fragment tiles, column-permuted,
//      q columns pre-scaled ----
__global__ void prep_w(const float* __restrict__ W) {
    for (int i = blockIdx.x * blockDim.x + threadIdx.x; i < 384 * 64;
         i += gridDim.x * blockDim.x) {
        const int o = i >> 6, kp = i & 63, k = kp * 2;
        const int op = permute_col(o);
        const float s = (op < 128) ? QSCALE : 1.0f;
        const float w0 = W[o * 128 + k] * s, w1 = W[o * 128 + k + 1] * s;
        uint32_t ph, pl;
        pack_hl(w0, w1, ph, pl);
        const int c8 = op >> 3, g = op & 7, kc = k >> 4, kk = k & 15;
        const int reg = (kk >= 8), j = (kk & 7) >> 1;
        const int pos = (((c8 * 8 + kc) * 32) + g * 4 + j) * 2 + reg;
        g_wfh[pos] = ph;
        g_wfl[pos] = pl;
    }
}

// ---- prep: fused bias+mask table g_bm[win][h][r*49+m] ----
__global__ void prep_bm(const float* __restrict__ mask,
                        const float* __restrict__ rel_table) {
    for (int i = blockIdx.x * blockDim.x + threadIdx.x; i < NWIN * NHEADS * 2401;
         i += gridDim.x * blockDim.x) {
        const int w = i / (NHEADS * 2401), rem = i - w * (NHEADS * 2401);
        const int h = rem / 2401, j = rem - h * 2401;
        const int r = j / 49, m = j - r * 49;
        const int ridx = (r / 7 - m / 7 + 6) * 13 + (r % 7 - m % 7 + 6);
        g_bm[i] = __ldg(&rel_table[ridx * NHEADS + h]) + __ldg(&mask[w * 2401 + j]);
    }
}

// epilogue writer for one 16-col tile (bias already in accumulators)
__device__ __forceinline__ void write_epilogue(char* sm, int tile, int g, int tq,
                                               float c[2][4][4]) {
    const int which = (tile * 16) >> 7;
    const int h     = ((tile * 16) >> 5) & 3;
    #pragma unroll
    for (int j = 0; j < 2; j++) {
        const int ocol = tile * 16 + j * 8 + tq * 2;
        const int d0   = ocol & 31;
        #pragma unroll
        for (int mt = 0; mt < 4; mt++) {
            #pragma unroll
            for (int half = 0; half < 2; half++) {
                const int n = mt * 16 + g + half * 8;
                if (n >= N_TOK) continue;
                const float v0 = c[j][mt][half * 2 + 0];
                const float v1 = c[j][mt][half * 2 + 1];
                uint32_t ph, pl;
                pack_hl(v0, v1, ph, pl);
                if (which == 0) {        // q A-frag: u32 granule over d
                    const int li = ((n & 7) << 2) | ((d0 & 7) >> 1);
                    const int reg = ((n & 15) >= 8 ? 1 : 0) + ((d0 & 15) >= 8 ? 2 : 0);
                    const int addr = ((((h * 4 + (n >> 4)) * 2 + (d0 >> 4)) * 32 + li) * 4 + reg) * 4;
                    *(uint32_t*)(sm + OFF_QFH + addr) = ph;
                    *(uint32_t*)(sm + OFF_QFL + addr) = pl;
                } else if (which == 1) { // k B-frag: u32 granule over d
                    const int li = ((n & 7) << 2) | ((d0 & 7) >> 1);
                    const int reg = ((d0 & 15) >= 8 ? 1 : 0);
                    const int addr = ((((h * 7 + (n >> 3)) * 2 + (d0 >> 4)) * 32 + li) * 2 + reg) * 4;
                    *(uint32_t*)(sm + OFF_KFH + addr) = ph;
                    *(uint32_t*)(sm + OFF_KFL + addr) = pl;
                } else {                 // v B-frag: granule pairs over n -> 2x b16 stores
                    const int reg = ((n & 15) >= 8 ? 1 : 0);
                    const int li0 = ((d0 & 7) << 2) | ((n & 7) >> 1);
                    const int a0 = ((((h * 4 + (n >> 4)) * 4 + (d0 >> 3)) * 32 + li0) * 2 + reg) * 4 + (n & 1) * 2;
                    *(unsigned short*)(sm + OFF_VFH + a0) = (unsigned short)(ph & 0xffff);
                    *(unsigned short*)(sm + OFF_VFL + a0) = (unsigned short)(pl & 0xffff);
                    const int d1 = d0 + 1;
                    const int li1 = ((d1 & 7) << 2) | ((n & 7) >> 1);
                    const int a1 = ((((h * 4 + (n >> 4)) * 4 + (d1 >> 3)) * 32 + li1) * 2 + reg) * 4 + (n & 1) * 2;
                    *(unsigned short*)(sm + OFF_VFH + a1) = (unsigned short)(ph >> 16);
                    *(unsigned short*)(sm + OFF_VFL + a1) = (unsigned short)(pl >> 16);
                }
            }
        }
    }
}

__device__ __forceinline__ void proj_tile(char* sm, int tile, int lane, int tq,
                                          const float* bvec_s, float c[2][4][4]) {
    // init accumulators with column bias (added exactly once per output)
    #pragma unroll
    for (int j = 0; j < 2; j++) {
        const int ocol = tile * 16 + j * 8 + tq * 2;
        const float b0 = bvec_s[ocol], b1 = bvec_s[ocol + 1];
        #pragma unroll
        for (int mt = 0; mt < 4; mt++) {
            c[j][mt][0] = b0; c[j][mt][1] = b1;
            c[j][mt][2] = b0; c[j][mt][3] = b1;
        }
    }

    const uint2* wfh = (const uint2*)g_wfh;
    const uint2* wfl = (const uint2*)g_wfl;
    #pragma unroll
    for (int kc = 0; kc < 8; kc++) {
        uint4 ah[4], al[4];
        #pragma unroll
        for (int mt = 0; mt < 4; mt++) {
            const int idx = (((mt * 8 + kc) * 32) + lane) << 4;
            ah[mt] = *(const uint4*)(sm + OFF_XH + idx);
            al[mt] = *(const uint4*)(sm + OFF_XL + idx);
        }
        uint2 bh[2], bl[2];
        #pragma unroll
        for (int j = 0; j < 2; j++) {
            const int idx = ((tile * 2 + j) * 8 + kc) * 32 + lane;
            bh[j] = __ldg(&wfh[idx]);
            bl[j] = __ldg(&wfl[idx]);
        }
        #pragma unroll
        for (int j = 0; j < 2; j++)
            #pragma unroll
            for (int mt = 0; mt < 4; mt++) {
                mma16816(c[j][mt], (const uint32_t*)&ah[mt], (const uint32_t*)&bh[j]);
                mma16816(c[j][mt], (const uint32_t*)&ah[mt], (const uint32_t*)&bl[j]);
                mma16816(c[j][mt], (const uint32_t*)&al[mt], (const uint32_t*)&bh[j]);
            }
    }
}

__global__ __launch_bounds__(THREADS, 2)
void win_attn_kernel(const float* __restrict__ x,
                     const float* __restrict__ bvec,
                     float* __restrict__ out)
{
    extern __shared__ char sm[];
    float* bvec_s = (float*)(sm + OFF_BVEC);

    const int t = threadIdx.x, wid = t >> 5, lane = t & 31;
    const int g = lane >> 2, tq = lane & 3;
    const int b = blockIdx.x;

    // ---- phase 0: stage bvec (permuted, q pre-scaled) + x frags (hi/lo) ----
    for (int i = t; i < 384; i += THREADS) {
        const int op = permute_col(i);
        bvec_s[op] = bvec[i] * ((op < 128) ? QSCALE : 1.0f);
    }
    {
        const float4* xg = (const float4*)(x + (size_t)b * 6272);
        uint32_t* xh = (uint32_t*)(sm + OFF_XH);
        uint32_t* xl = (uint32_t*)(sm + OFF_XL);
        for (int i = t; i < 64 * 32; i += THREADS) {
            const int r = i >> 5, k0 = (i & 31) * 4;
            float4 v = make_float4(0.f, 0.f, 0.f, 0.f);
            if (r < N_TOK) v = xg[r * 32 + (i & 31)];
            const uint32_t ph01 = cvt2(v.x, v.y);
            const uint32_t ph23 = cvt2(v.z, v.w);
            const uint32_t pl01 = cvt2(v.x - bf_lo(ph01), v.y - bf_hi(ph01));
            const uint32_t pl23 = cvt2(v.z - bf_lo(ph23), v.w - bf_hi(ph23));
            const int mt = r >> 4, r16 = r & 15, g8 = r16 & 7;
            const int kc = k0 >> 4, kk = k0 & 15;
            const int reg = (r16 >= 8 ? 1 : 0) + (kk >= 8 ? 2 : 0);
            const int jj = (kk & 7) >> 1;
            const int base = (((mt * 8 + kc) * 32) + g8 * 4 + jj) * 4 + reg;
            xh[base] = ph01; xh[base + 4] = ph23;
            xl[base] = pl01; xl[base + 4] = pl23;
        }
    }
    __syncthreads();

    // ---- phase 1: projection, 24 tiles of 16 cols over 12 warps, 2 passes ----
    float c[2][4][4];
    // pass A: tiles 0-11 (q cols 0-127, k cols 128-191) -> immediate epilogue
    proj_tile(sm, wid, lane, tq, bvec_s, c);
    write_epilogue(sm, wid, g, tq, c);
    // pass B: tiles 12-23; warps 0-3 -> k (immediate); warps 4-11 -> v (DEFERRED,
    // VF aliases XH/XL so writes must wait until all A-frag reads complete)
    proj_tile(sm, 12 + wid, lane, tq, bvec_s, c);
    if (wid < 4) write_epilogue(sm, 12 + wid, g, tq, c);
    __syncthreads();                       // all A-frag reads done
    if (wid >= 4) write_epilogue(sm, 12 + wid, g, tq, c);
    __syncthreads();                       // q/k/v frags ready

    // ---- phase 2: attention, 16 (head, 16-row tile) tasks over 12 warps ----
    for (int task = wid; task < 16; task += 12) {
        const int h = task >> 2, mt = task & 3;
        const int r0 = mt * 16 + g, r1 = r0 + 8;
        const float* bmg = g_bm + ((size_t)(b & (NWIN - 1)) * NHEADS + h) * 2401;

        // q A-frags
        uint4 ah[2], al[2];
        #pragma unroll
        for (int kc = 0; kc < 2; kc++) {
            const int idx = (((h * 4 + mt) * 2 + kc) * 32 + lane) << 4;
            ah[kc] = *(const uint4*)(sm + OFF_QFH + idx);
            al[kc] = *(const uint4*)(sm + OFF_QFL + idx);
        }

        // S = q k^T; c2[8] covers keys 0-63 (nt=7 has no K data -> masked)
        float c2[8][4];
        #pragma unroll
        for (int nt = 0; nt < 8; nt++)
            #pragma unroll
            for (int e = 0; e < 4; e++) c2[nt][e] = 0.f;

        #pragma unroll
        for (int nt = 0; nt < 7; nt++)
            #pragma unroll
            for (int kc = 0; kc < 2; kc++) {
                const int idx = (((h * 7 + nt) * 2 + kc) * 32 + lane) << 3;
                const uint2 bh = *(const uint2*)(sm + OFF_KFH + idx);
                const uint2 bl = *(const uint2*)(sm + OFF_KFL + idx);
                mma16816(c2[nt], (const uint32_t*)&ah[kc], (const uint32_t*)&bh);
                mma16816(c2[nt], (const uint32_t*)&ah[kc], (const uint32_t*)&bl);
                mma16816(c2[nt], (const uint32_t*)&al[kc], (const uint32_t*)&bh);
            }

        // fused bias+mask (L2-resident table); mask out padding keys/rows
        #pragma unroll
        for (int nt = 0; nt < 8; nt++)
            #pragma unroll
            for (int e = 0; e < 4; e++) {
                const int r = (e >= 2) ? r1 : r0;
                const int m = nt * 8 + tq * 2 + (e & 1);
                if (m < N_TOK && r < N_TOK)
                    c2[nt][e] += __ldg(&bmg[r * 49 + m]);
                else
                    c2[nt][e] = -1e30f;
            }

        // softmax across the 4-lane group (rows r0: e=0,1; r1: e=2,3)
        float mx0 = -1e30f, mx1 = -1e30f;
        #pragma unroll
        for (int nt = 0; nt < 8; nt++) {
            mx0 = fmaxf(mx0, fmaxf(c2[nt][0], c2[nt][1]));
            mx1 = fmaxf(mx1, fmaxf(c2[nt][2], c2[nt][3]));
        }
        mx0 = fmaxf(mx0, __shfl_xor_sync(~0u, mx0, 1));
        mx0 = fmaxf(mx0, __shfl_xor_sync(~0u, mx0, 2));
        mx1 = fmaxf(mx1, __shfl_xor_sync(~0u, mx1, 1));
        mx1 = fmaxf(mx1, __shfl_xor_sync(~0u, mx1, 2));
        float s0 = 0.f, s1 = 0.f;
        #pragma unroll
        for (int nt = 0; nt < 8; nt++) {
            c2[nt][0] = __expf(c2[nt][0] - mx0); s0 += c2[nt][0];
            c2[nt][1] = __expf(c2[nt][1] - mx0); s0 += c2[nt][1];
            c2[nt][2] = __expf(c2[nt][2] - mx1); s1 += c2[nt][2];
            c2[nt][3] = __expf(c2[nt][3] - mx1); s1 += c2[nt][3];
        }
        s0 += __shfl_xor_sync(~0u, s0, 1);
        s0 += __shfl_xor_sync(~0u, s0, 2);
        s1 += __shfl_xor_sync(~0u, s1, 1);
        s1 += __shfl_xor_sync(~0u, s1, 2);
        const float inv0 = 1.f / s0, inv1 = 1.f / s1;
        #pragma unroll
        for (int nt = 0; nt < 8; nt++) {
            c2[nt][0] *= inv0; c2[nt][1] *= inv0;
            c2[nt][2] *= inv1; c2[nt][3] *= inv1;
        }

        // PV: P (c-frags -> A-frags in registers) x V (B-frags)
        float o_[4][4];
        #pragma unroll
        for (int nd = 0; nd < 4; nd++)
            #pragma unroll
            for (int e = 0; e < 4; e++) o_[nd][e] = 0.f;

        #pragma unroll
        for (int kck = 0; kck < 4; kck++) {
            uint32_t pah[4], pal[4];
            pack_hl(c2[2 * kck][0],     c2[2 * kck][1],     pah[0], pal[0]);
            pack_hl(c2[2 * kck][2],     c2[2 * kck][3],     pah[1], pal[1]);
            pack_hl(c2[2 * kck + 1][0], c2[2 * kck + 1][1], pah[2], pal[2]);
            pack_hl(c2[2 * kck + 1][2], c2[2 * kck + 1][3], pah[3], pal[3]);
            #pragma unroll
            for (int nd = 0; nd < 4; nd++) {
                const int idx = (((h * 4 + kck) * 4 + nd) * 32 + lane) << 3;
                const uint2 vh = *(const uint2*)(sm + OFF_VFH + idx);
                const uint2 vl = *(const uint2*)(sm + OFF_VFL + idx);
                mma16816(o_[nd], pah, (const uint32_t*)&vh);
                mma16816(o_[nd], pah, (const uint32_t*)&vl);
                mma16816(o_[nd], pal, (const uint32_t*)&vh);
            }
        }

        // writeback
        float* ob = out + (size_t)b * 6272 + h * 32;
        #pragma unroll
        for (int nd = 0; nd < 4; nd++) {
            const int d0 = nd * 8 + tq * 2;
            if (r0 < N_TOK)
                *(float2*)(ob + r0 * 128 + d0) = make_float2(o_[nd][0], o_[nd][1]);
            if (r1 < N_TOK)
                *(float2*)(ob + r1 * 128 + d0) = make_float2(o_[nd][2], o_[nd][3]);
        }
    }
}

extern "C" void kernel_launch(void* const* d_in, const int* in_sizes, int n_in,
                              void* d_out, int out_size)
{
    const float* x    = (const float*)d_in[0];
    const float* mask = (const float*)d_in[1];
    const float* W    = (const float*)d_in[2];
    const float* bvec = (const float*)d_in[3];
    const float* rel  = (const float*)d_in[4];
    float* out = (float*)d_out;

    prep_w<<<96, 256>>>(W);
    prep_bm<<<512, 256>>>(mask, rel);
    cudaFuncSetAttribute(win_attn_kernel,
                         cudaFuncAttributeMaxDynamicSharedMemorySize, SMEM_TOTAL);
    win_attn_kernel<<<4096, THREADS, SMEM_TOTAL>>>(x, bvec, out);
}